// round 1
// baseline (speedup 1.0000x reference)
#include <cuda_runtime.h>

// ---------------------------------------------------------------------------
// GCN 2-layer: h1 = relu(scatterAdd(norm * (x@W1)[src] -> dst) + selfloop + b1)
//              out = log_softmax(scatterAdd(norm * (h1@W2)[src] -> dst) + selfloop + b2)
// norm = dinv[src]*dinv[dst], dinv = rsqrt(deg), deg = in-degree incl. self-loop
// ---------------------------------------------------------------------------

#define MAXN 131072
#define IN_CH 256
#define HID 64
#define OUT_CH 16

__device__ float g_h1[(size_t)MAXN * HID];
__device__ float g_out1[(size_t)MAXN * HID];
__device__ float g_h2[(size_t)MAXN * OUT_CH];
__device__ float g_deg[MAXN];
__device__ float g_dinv[MAXN];
__device__ int   g_is64;

// ---- edge index load, dtype decided at runtime ----------------------------
__device__ __forceinline__ int ldidx(const void* ei, long long i, int is64) {
    if (is64) return (int)__ldg(((const long long*)ei) + i);
    return __ldg(((const int*)ei) + i);
}

// Probe: interpret first ncheck words as int64. If data is really int32, the
// packed (lo,hi) pairs are almost surely out of [0,N) range -> is64=0.
__global__ void k_detect(const void* ei, int ncheck, int N) {
    if (threadIdx.x == 0 && blockIdx.x == 0) {
        const long long* p = (const long long*)ei;
        int ok = 1;
        for (int i = 0; i < ncheck; i++) {
            long long v = p[i];
            if (v < 0 || v >= (long long)N) { ok = 0; break; }
        }
        g_is64 = ok;
    }
}

// ---- degree / normalization -----------------------------------------------
__global__ void k_deg_init(int N) {
    int i = blockIdx.x * blockDim.x + threadIdx.x;
    if (i < N) g_deg[i] = 1.0f;  // self-loop
}

__global__ void k_deg_edges(const void* ei, long long E) {
    long long e = (long long)blockIdx.x * blockDim.x + threadIdx.x;
    if (e >= E) return;
    int is64 = g_is64;
    int d = ldidx(ei, E + e, is64);
    atomicAdd(&g_deg[d], 1.0f);
}

__global__ void k_dinv(int N) {
    int i = blockIdx.x * blockDim.x + threadIdx.x;
    if (i < N) g_dinv[i] = rsqrtf(g_deg[i]);
}

// ---- GEMM1: h1[N,64] = x[N,256] @ W1[256,64] ------------------------------
// Block = 256 threads, 16 nodes per block, K tiled by 128.
__global__ void k_gemm1(const float* __restrict__ x, const float* __restrict__ W1, int N) {
    __shared__ float Ws[128 * 64];     // 32 KB
    __shared__ float xs[16][128];      //  8 KB
    int tid = threadIdx.x;
    int f  = tid & 63;
    int ng = tid >> 6;                 // 0..3
    int node0 = blockIdx.x * 16;
    float acc[4] = {0.f, 0.f, 0.f, 0.f};

    for (int kk = 0; kk < IN_CH; kk += 128) {
        for (int i = tid; i < 128 * 64; i += 256)
            Ws[i] = W1[(size_t)(kk + (i >> 6)) * 64 + (i & 63)];
        for (int i = tid; i < 16 * 128; i += 256) {
            int n = i >> 7, k = i & 127;
            int node = node0 + n;
            xs[n][k] = (node < N) ? x[(size_t)node * IN_CH + kk + k] : 0.f;
        }
        __syncthreads();
        #pragma unroll 16
        for (int k = 0; k < 128; k++) {
            float w = Ws[k * 64 + f];
            acc[0] += xs[ng * 4 + 0][k] * w;
            acc[1] += xs[ng * 4 + 1][k] * w;
            acc[2] += xs[ng * 4 + 2][k] * w;
            acc[3] += xs[ng * 4 + 3][k] * w;
        }
        __syncthreads();
    }
    #pragma unroll
    for (int j = 0; j < 4; j++) {
        int node = node0 + ng * 4 + j;
        if (node < N) g_h1[(size_t)node * HID + f] = acc[j];
    }
}

// ---- vector L2 reduction --------------------------------------------------
__device__ __forceinline__ void red4(float* p, float4 v) {
    asm volatile("red.global.add.v4.f32 [%0], {%1,%2,%3,%4};"
                 :: "l"(p), "f"(v.x), "f"(v.y), "f"(v.z), "f"(v.w) : "memory");
}

// ---- layer-1 aggregation --------------------------------------------------
// init: out1 = dinv^2 * h1 (self-loop contribution)
__global__ void k_init1(int N) {
    int t = blockIdx.x * blockDim.x + threadIdx.x;   // over N*16 float4s
    if (t >= N * 16) return;
    int node = t >> 4;
    float s = g_dinv[node]; s = s * s;
    float4 v = ((const float4*)g_h1)[t];
    v.x *= s; v.y *= s; v.z *= s; v.w *= s;
    ((float4*)g_out1)[t] = v;
}

// one thread per (edge, 4-feature chunk): 16 chunks/edge
__global__ void k_scatter1(const void* ei, long long E) {
    long long t = (long long)blockIdx.x * blockDim.x + threadIdx.x;
    if (t >= E * 16) return;
    long long e = t >> 4;
    int c = (int)(t & 15);
    int is64 = g_is64;
    int s = ldidx(ei, e, is64);
    int d = ldidx(ei, E + e, is64);
    float norm = g_dinv[s] * g_dinv[d];
    float4 v = ((const float4*)(g_h1 + (size_t)s * HID))[c];
    v.x *= norm; v.y *= norm; v.z *= norm; v.w *= norm;
    red4(g_out1 + (size_t)d * HID + c * 4, v);
}

__global__ void k_relu_bias(const float* __restrict__ b1, int N) {
    int t = blockIdx.x * blockDim.x + threadIdx.x;   // over N*16 float4s
    if (t >= N * 16) return;
    int c = t & 15;
    float4 v = ((const float4*)g_out1)[t];
    float4 b = ((const float4*)b1)[c];
    v.x = fmaxf(v.x + b.x, 0.f);
    v.y = fmaxf(v.y + b.y, 0.f);
    v.z = fmaxf(v.z + b.z, 0.f);
    v.w = fmaxf(v.w + b.w, 0.f);
    ((float4*)g_out1)[t] = v;
}

// ---- GEMM2: h2[N,16] = out1[N,64] @ W2[64,16] -----------------------------
__global__ void k_gemm2(const float* __restrict__ W2, int N) {
    __shared__ float Ws[64 * 16];
    __shared__ float ts[16][64];
    int tid = threadIdx.x;
    for (int i = tid; i < 64 * 16; i += 256) Ws[i] = W2[i];
    int node0 = blockIdx.x * 16;
    for (int i = tid; i < 16 * 64; i += 256) {
        int n = i >> 6, k = i & 63;
        int node = node0 + n;
        ts[n][k] = (node < N) ? g_out1[(size_t)node * HID + k] : 0.f;
    }
    __syncthreads();
    int f = tid & 15, n = tid >> 4;
    float acc = 0.f;
    #pragma unroll 16
    for (int k = 0; k < 64; k++) acc += ts[n][k] * Ws[k * 16 + f];
    int node = node0 + n;
    if (node < N) g_h2[(size_t)node * OUT_CH + f] = acc;
}

// ---- layer-2 aggregation (into d_out) -------------------------------------
__global__ void k_init2(float* __restrict__ out, int N) {
    int t = blockIdx.x * blockDim.x + threadIdx.x;   // over N*4 float4s
    if (t >= N * 4) return;
    int node = t >> 2;
    float s = g_dinv[node]; s = s * s;
    float4 v = ((const float4*)g_h2)[t];
    v.x *= s; v.y *= s; v.z *= s; v.w *= s;
    ((float4*)out)[t] = v;
}

__global__ void k_scatter2(const void* ei, float* __restrict__ out, long long E) {
    long long t = (long long)blockIdx.x * blockDim.x + threadIdx.x;
    if (t >= E * 4) return;
    long long e = t >> 2;
    int c = (int)(t & 3);
    int is64 = g_is64;
    int s = ldidx(ei, e, is64);
    int d = ldidx(ei, E + e, is64);
    float norm = g_dinv[s] * g_dinv[d];
    float4 v = ((const float4*)(g_h2 + (size_t)s * OUT_CH))[c];
    v.x *= norm; v.y *= norm; v.z *= norm; v.w *= norm;
    red4(out + (size_t)d * OUT_CH + c * 4, v);
}

// ---- bias + log_softmax (in place on d_out) -------------------------------
__global__ void k_final(float* __restrict__ out, const float* __restrict__ b2, int N) {
    int node = blockIdx.x * blockDim.x + threadIdx.x;
    if (node >= N) return;
    float4* p = (float4*)(out + (size_t)node * OUT_CH);
    const float4* bb = (const float4*)b2;
    float v[16];
    #pragma unroll
    for (int i = 0; i < 4; i++) {
        float4 a = p[i], b = bb[i];
        v[4 * i + 0] = a.x + b.x;
        v[4 * i + 1] = a.y + b.y;
        v[4 * i + 2] = a.z + b.z;
        v[4 * i + 3] = a.w + b.w;
    }
    float m = v[0];
    #pragma unroll
    for (int i = 1; i < 16; i++) m = fmaxf(m, v[i]);
    float s = 0.f;
    #pragma unroll
    for (int i = 0; i < 16; i++) s += expf(v[i] - m);
    float l = m + logf(s);
    #pragma unroll
    for (int i = 0; i < 4; i++) {
        float4 a;
        a.x = v[4 * i + 0] - l;
        a.y = v[4 * i + 1] - l;
        a.z = v[4 * i + 2] - l;
        a.w = v[4 * i + 3] - l;
        p[i] = a;
    }
}

// ---------------------------------------------------------------------------
extern "C" void kernel_launch(void* const* d_in, const int* in_sizes, int n_in,
                              void* d_out, int out_size) {
    const float* x  = (const float*)d_in[0];
    const void*  ei = d_in[1];
    const float* W1 = (const float*)d_in[2];
    const float* b1 = (const float*)d_in[3];
    const float* W2 = (const float*)d_in[4];
    const float* b2 = (const float*)d_in[5];
    float* out = (float*)d_out;

    int N = in_sizes[0] / IN_CH;
    long long E = in_sizes[1] / 2;

    int ncheck = (int)((E < 2048) ? E : 2048);
    k_detect<<<1, 32>>>(ei, ncheck, N);

    int nbN = (N + 255) / 256;
    k_deg_init<<<nbN, 256>>>(N);
    k_deg_edges<<<(int)((E + 255) / 256), 256>>>(ei, E);
    k_dinv<<<nbN, 256>>>(N);

    k_gemm1<<<(N + 15) / 16, 256>>>(x, W1, N);
    k_init1<<<(N * 16 + 255) / 256, 256>>>(N);
    k_scatter1<<<(int)((E * 16 + 255) / 256), 256>>>(ei, E);
    k_relu_bias<<<(N * 16 + 255) / 256, 256>>>(b1, N);

    k_gemm2<<<(N + 15) / 16, 256>>>(W2, N);
    k_init2<<<(N * 4 + 255) / 256, 256>>>(out, N);
    k_scatter2<<<(int)((E * 4 + 255) / 256), 256>>>(ei, out, E);
    k_final<<<nbN, 256>>>(out, b2, N);
}

// round 2
// speedup vs baseline: 1.2934x; 1.2934x over previous
#include <cuda_runtime.h>

// ---------------------------------------------------------------------------
// GCN 2-layer, round 2: register-tiled GEMM1, edge packing + precomputed norm,
// fused init/bias/relu passes.
// ---------------------------------------------------------------------------

#define MAXN 131072
#define MAXE 4194304
#define IN_CH 256
#define HID 64
#define OUT_CH 16

__device__ float g_h1[(size_t)MAXN * HID];
__device__ float g_out1[(size_t)MAXN * HID];
__device__ float g_h2[(size_t)MAXN * OUT_CH];
__device__ float g_deg[MAXN];
__device__ float g_dinv[MAXN];
__device__ int2  g_edge[MAXE];
__device__ float g_norm[MAXE];
__device__ int   g_is64;

// ---- edge index load, dtype decided at runtime ----------------------------
__device__ __forceinline__ int ldidx(const void* ei, long long i, int is64) {
    if (is64) return (int)__ldg(((const long long*)ei) + i);
    return __ldg(((const int*)ei) + i);
}

// Probe: interpret first ncheck words as int64. If data is really int32, the
// packed (lo,hi) pairs are almost surely out of [0,N) range -> is64=0.
__global__ void k_detect(const void* ei, int ncheck, int N) {
    if (threadIdx.x == 0 && blockIdx.x == 0) {
        const long long* p = (const long long*)ei;
        int ok = 1;
        for (int i = 0; i < ncheck; i++) {
            long long v = p[i];
            if (v < 0 || v >= (long long)N) { ok = 0; break; }
        }
        g_is64 = ok;
    }
}

__global__ void k_deg_init(int N) {
    int i = blockIdx.x * blockDim.x + threadIdx.x;
    if (i < N) g_deg[i] = 1.0f;  // self-loop
}

// decode edge index once -> packed int2, accumulate in-degree
__global__ void k_prep(const void* ei, long long E) {
    long long e = (long long)blockIdx.x * blockDim.x + threadIdx.x;
    if (e >= E) return;
    int is64 = g_is64;
    int s = ldidx(ei, e, is64);
    int d = ldidx(ei, E + e, is64);
    g_edge[e] = make_int2(s, d);
    atomicAdd(&g_deg[d], 1.0f);
}

__global__ void k_dinv(int N) {
    int i = blockIdx.x * blockDim.x + threadIdx.x;
    if (i < N) g_dinv[i] = rsqrtf(g_deg[i]);
}

__global__ void k_norm(long long E) {
    long long e = (long long)blockIdx.x * blockDim.x + threadIdx.x;
    if (e >= E) return;
    int2 ed = g_edge[e];
    g_norm[e] = g_dinv[ed.x] * g_dinv[ed.y];
}

// ---- GEMM1: h1[N,64] = x[N,256] @ W1[256,64], register-tiled --------------
// Block tile 64 nodes x 64 feats, 256 threads, thread tile 4x4, K tile 32.
// Epilogue also writes out1 = dinv^2 * h1 (self-loop init, fused).
#define KT 32
__global__ __launch_bounds__(256) void k_gemm1(const float* __restrict__ x,
                                               const float* __restrict__ W1, int N) {
    __shared__ float Xs[KT][68];   // [k][node], stride 68 keeps float4 align
    __shared__ float Ws[KT][64];   // [k][feat]
    int tid = threadIdx.x;
    int node0 = blockIdx.x * 64;
    int na = (tid & 15) * 4;       // node offset of 4-node group
    int fb = (tid >> 4) * 4;       // feature offset of 4-feat group

    float acc[4][4];
    #pragma unroll
    for (int i = 0; i < 4; i++)
        #pragma unroll
        for (int j = 0; j < 4; j++) acc[i][j] = 0.f;

    int ldnode = tid >> 3;         // 0..31
    int kq = tid & 7;              // float4 index along k

    for (int kk = 0; kk < IN_CH; kk += KT) {
        // W tile: KT*64 floats = 512 float4, contiguous
        {
            const float4* wg = (const float4*)(W1 + (size_t)kk * 64);
            float4* wsv = (float4*)Ws;
            wsv[tid] = wg[tid];
            wsv[tid + 256] = wg[tid + 256];
        }
        // X tile, transposed into Xs[k][node]
        #pragma unroll
        for (int half = 0; half < 2; half++) {
            int n = ldnode + half * 32;
            int gnode = node0 + n;
            float4 v = (gnode < N)
                ? *(const float4*)(x + (size_t)gnode * IN_CH + kk + kq * 4)
                : make_float4(0.f, 0.f, 0.f, 0.f);
            Xs[kq * 4 + 0][n] = v.x;
            Xs[kq * 4 + 1][n] = v.y;
            Xs[kq * 4 + 2][n] = v.z;
            Xs[kq * 4 + 3][n] = v.w;
        }
        __syncthreads();
        #pragma unroll
        for (int k = 0; k < KT; k++) {
            float4 a = *(const float4*)&Xs[k][na];
            float4 b = *(const float4*)&Ws[k][fb];
            acc[0][0] += a.x * b.x; acc[0][1] += a.x * b.y;
            acc[0][2] += a.x * b.z; acc[0][3] += a.x * b.w;
            acc[1][0] += a.y * b.x; acc[1][1] += a.y * b.y;
            acc[1][2] += a.y * b.z; acc[1][3] += a.y * b.w;
            acc[2][0] += a.z * b.x; acc[2][1] += a.z * b.y;
            acc[2][2] += a.z * b.z; acc[2][3] += a.z * b.w;
            acc[3][0] += a.w * b.x; acc[3][1] += a.w * b.y;
            acc[3][2] += a.w * b.z; acc[3][3] += a.w * b.w;
        }
        __syncthreads();
    }
    #pragma unroll
    for (int i = 0; i < 4; i++) {
        int node = node0 + na + i;
        if (node < N) {
            float s = g_dinv[node]; s = s * s;
            float4 h = make_float4(acc[i][0], acc[i][1], acc[i][2], acc[i][3]);
            *(float4*)(g_h1 + (size_t)node * HID + fb) = h;
            float4 o = make_float4(h.x * s, h.y * s, h.z * s, h.w * s);
            *(float4*)(g_out1 + (size_t)node * HID + fb) = o;
        }
    }
}

// ---- vector L2 reduction --------------------------------------------------
__device__ __forceinline__ void red4(float* p, float4 v) {
    asm volatile("red.global.add.v4.f32 [%0], {%1,%2,%3,%4};"
                 :: "l"(p), "f"(v.x), "f"(v.y), "f"(v.z), "f"(v.w) : "memory");
}

// ---- layer-1 scatter: 16 chunk-threads per edge ---------------------------
__global__ void k_scatter1(long long E) {
    long long t = (long long)blockIdx.x * blockDim.x + threadIdx.x;
    if (t >= E * 16) return;
    long long e = t >> 4;
    int c = (int)(t & 15);
    int2 ed = g_edge[e];
    float nrm = g_norm[e];
    float4 v = ((const float4*)(g_h1 + (size_t)ed.x * HID))[c];
    v.x *= nrm; v.y *= nrm; v.z *= nrm; v.w *= nrm;
    red4(g_out1 + (size_t)ed.y * HID + c * 4, v);
}

// ---- GEMM2: h2[N,16] = relu(out1+b1)[N,64] @ W2[64,16] --------------------
// bias+relu fused on smem load; epilogue writes h2 and out = dinv^2*h2.
__global__ __launch_bounds__(256) void k_gemm2(const float* __restrict__ W2,
                                               const float* __restrict__ b1,
                                               float* __restrict__ out, int N) {
    __shared__ float Ws[64 * 16];
    __shared__ float ts[16][68];
    __shared__ float bs[64];
    int tid = threadIdx.x;
    for (int i = tid; i < 64 * 16; i += 256) Ws[i] = W2[i];
    if (tid < 64) bs[tid] = b1[tid];
    int node0 = blockIdx.x * 16;
    __syncthreads();
    for (int i = tid; i < 16 * 64; i += 256) {
        int n = i >> 6, k = i & 63;
        int node = node0 + n;
        float v = (node < N) ? g_out1[(size_t)node * HID + k] + bs[k] : 0.f;
        ts[n][k] = fmaxf(v, 0.f);
    }
    __syncthreads();
    int f = tid & 15, n = tid >> 4;
    float accv = 0.f;
    #pragma unroll 16
    for (int k = 0; k < 64; k++) accv += ts[n][k] * Ws[k * 16 + f];
    int node = node0 + n;
    if (node < N) {
        float s = g_dinv[node]; s = s * s;
        g_h2[(size_t)node * OUT_CH + f] = accv;
        out[(size_t)node * OUT_CH + f] = accv * s;
    }
}

// ---- layer-2 scatter ------------------------------------------------------
__global__ void k_scatter2(float* __restrict__ out, long long E) {
    long long t = (long long)blockIdx.x * blockDim.x + threadIdx.x;
    if (t >= E * 4) return;
    long long e = t >> 2;
    int c = (int)(t & 3);
    int2 ed = g_edge[e];
    float nrm = g_norm[e];
    float4 v = ((const float4*)(g_h2 + (size_t)ed.x * OUT_CH))[c];
    v.x *= nrm; v.y *= nrm; v.z *= nrm; v.w *= nrm;
    red4(out + (size_t)ed.y * OUT_CH + c * 4, v);
}

// ---- bias + log_softmax (in place on d_out) -------------------------------
__global__ void k_final(float* __restrict__ out, const float* __restrict__ b2, int N) {
    int node = blockIdx.x * blockDim.x + threadIdx.x;
    if (node >= N) return;
    float4* p = (float4*)(out + (size_t)node * OUT_CH);
    const float4* bb = (const float4*)b2;
    float v[16];
    #pragma unroll
    for (int i = 0; i < 4; i++) {
        float4 a = p[i], b = bb[i];
        v[4 * i + 0] = a.x + b.x;
        v[4 * i + 1] = a.y + b.y;
        v[4 * i + 2] = a.z + b.z;
        v[4 * i + 3] = a.w + b.w;
    }
    float m = v[0];
    #pragma unroll
    for (int i = 1; i < 16; i++) m = fmaxf(m, v[i]);
    float s = 0.f;
    #pragma unroll
    for (int i = 0; i < 16; i++) s += expf(v[i] - m);
    float l = m + logf(s);
    #pragma unroll
    for (int i = 0; i < 4; i++) {
        float4 a;
        a.x = v[4 * i + 0] - l;
        a.y = v[4 * i + 1] - l;
        a.z = v[4 * i + 2] - l;
        a.w = v[4 * i + 3] - l;
        p[i] = a;
    }
}

// ---------------------------------------------------------------------------
extern "C" void kernel_launch(void* const* d_in, const int* in_sizes, int n_in,
                              void* d_out, int out_size) {
    const float* x  = (const float*)d_in[0];
    const void*  ei = d_in[1];
    const float* W1 = (const float*)d_in[2];
    const float* b1 = (const float*)d_in[3];
    const float* W2 = (const float*)d_in[4];
    const float* b2 = (const float*)d_in[5];
    float* out = (float*)d_out;

    int N = in_sizes[0] / IN_CH;
    long long E = in_sizes[1] / 2;

    int ncheck = (int)((E < 2048) ? E : 2048);
    int nbN = (N + 255) / 256;
    int nbE = (int)((E + 255) / 256);

    k_detect<<<1, 32>>>(ei, ncheck, N);                       // launch 1
    k_deg_init<<<nbN, 256>>>(N);                              // launch 2
    k_prep<<<nbE, 256>>>(ei, E);                              // launch 3
    k_dinv<<<nbN, 256>>>(N);                                  // launch 4
    k_norm<<<nbE, 256>>>(E);                                  // launch 5
    k_gemm1<<<(N + 63) / 64, 256>>>(x, W1, N);                // launch 6 (ncu window)
    k_scatter1<<<(int)((E * 16 + 255) / 256), 256>>>(E);      // launch 7
    k_gemm2<<<(N + 15) / 16, 256>>>(W2, b1, out, N);          // launch 8
    k_scatter2<<<(int)((E * 4 + 255) / 256), 256>>>(out, E);  // launch 9
    k_final<<<nbN, 256>>>(out, b2, N);                        // launch 10
}

// round 3
// speedup vs baseline: 1.5720x; 1.2154x over previous
#include <cuda_runtime.h>

// ---------------------------------------------------------------------------
// GCN 2-layer, round 3: destination-CSR gather (no float atomics), fused
// self-loop/bias/relu, register-tiled GEMM1.
// ---------------------------------------------------------------------------

#define MAXN 131072
#define MAXE 4194304
#define IN_CH 256
#define HID 64
#define OUT_CH 16

__device__ float g_h1[(size_t)MAXN * HID];
__device__ float g_out1[(size_t)MAXN * HID];
__device__ float g_h2[(size_t)MAXN * OUT_CH];
__device__ float g_dinv[MAXN];
__device__ int   g_incnt[MAXN];
__device__ int   g_rowstart[MAXN];
__device__ int   g_fill[MAXN];
__device__ int   g_blocksum[1024];
__device__ int2  g_edge[MAXE];   // decoded (src, dst)
__device__ int2  g_csr[MAXE];    // (src, norm-as-bits) grouped by dst
__device__ int   g_is64;

// ---- edge index load, dtype decided at runtime ----------------------------
__device__ __forceinline__ int ldidx(const void* ei, long long i, int is64) {
    if (is64) return (int)__ldg(((const long long*)ei) + i);
    return __ldg(((const int*)ei) + i);
}

__global__ void k_detect(const void* ei, int ncheck, int N) {
    if (threadIdx.x == 0 && blockIdx.x == 0) {
        const long long* p = (const long long*)ei;
        int ok = 1;
        for (int i = 0; i < ncheck; i++) {
            long long v = p[i];
            if (v < 0 || v >= (long long)N) { ok = 0; break; }
        }
        g_is64 = ok;
    }
}

__global__ void k_zero(int N) {
    int i = blockIdx.x * blockDim.x + threadIdx.x;
    if (i < N) g_incnt[i] = 0;
}

// decode edge index once -> packed int2, accumulate in-degree (int atomics)
__global__ void k_prep(const void* ei, long long E) {
    long long e = (long long)blockIdx.x * blockDim.x + threadIdx.x;
    if (e >= E) return;
    int is64 = g_is64;
    int s = ldidx(ei, e, is64);
    int d = ldidx(ei, E + e, is64);
    g_edge[e] = make_int2(s, d);
    atomicAdd(&g_incnt[d], 1);
}

__global__ void k_dinv(int N) {
    int i = blockIdx.x * blockDim.x + threadIdx.x;
    if (i < N) g_dinv[i] = rsqrtf((float)(g_incnt[i] + 1));  // +1 self-loop
}

// ---- 3-step exclusive scan of g_incnt -> g_rowstart -----------------------
__global__ void k_scan_block(int N) {
    __shared__ int wsum[8];
    int tid = threadIdx.x;
    int i = blockIdx.x * 256 + tid;
    int v = (i < N) ? g_incnt[i] : 0;
    int lane = tid & 31, wid = tid >> 5;
    int x = v;
    #pragma unroll
    for (int o = 1; o < 32; o <<= 1) {
        int y = __shfl_up_sync(0xffffffffu, x, o);
        if (lane >= o) x += y;
    }
    if (lane == 31) wsum[wid] = x;
    __syncthreads();
    if (wid == 0) {
        int s = (lane < 8) ? wsum[lane] : 0;
        #pragma unroll
        for (int o = 1; o < 8; o <<= 1) {
            int y = __shfl_up_sync(0xffffffffu, s, o);
            if (lane >= o) s += y;
        }
        if (lane < 8) wsum[lane] = s;
    }
    __syncthreads();
    int excl = x - v + (wid > 0 ? wsum[wid - 1] : 0);
    if (i < N) g_rowstart[i] = excl;
    if (tid == 255) g_blocksum[blockIdx.x] = excl + v;
}

__global__ void k_scan_sums(int nb) {
    __shared__ int sh[512];
    int tid = threadIdx.x;
    int v = (tid < nb) ? g_blocksum[tid] : 0;
    sh[tid] = v;
    __syncthreads();
    for (int o = 1; o < 512; o <<= 1) {
        int y = (tid >= o) ? sh[tid - o] : 0;
        __syncthreads();
        sh[tid] += y;
        __syncthreads();
    }
    if (tid < nb) g_blocksum[tid] = sh[tid] - v;  // exclusive
}

__global__ void k_scan_add(int N) {
    int i = blockIdx.x * 256 + threadIdx.x;
    if (i < N) {
        int r = g_rowstart[i] + g_blocksum[blockIdx.x];
        g_rowstart[i] = r;
        g_fill[i] = r;
    }
}

// ---- fill CSR: (src, norm) grouped by dst ---------------------------------
__global__ void k_fill(long long E) {
    long long e = (long long)blockIdx.x * blockDim.x + threadIdx.x;
    if (e >= E) return;
    int2 ed = g_edge[e];
    float nrm = g_dinv[ed.x] * g_dinv[ed.y];
    int pos = atomicAdd(&g_fill[ed.y], 1);
    g_csr[pos] = make_int2(ed.x, __float_as_int(nrm));
}

// ---- GEMM1: h1[N,64] = x[N,256] @ W1[256,64], register-tiled --------------
#define KT 32
__global__ __launch_bounds__(256) void k_gemm1(const float* __restrict__ x,
                                               const float* __restrict__ W1, int N) {
    __shared__ float Xs[KT][68];
    __shared__ float Ws[KT][64];
    int tid = threadIdx.x;
    int node0 = blockIdx.x * 64;
    int na = (tid & 15) * 4;
    int fb = (tid >> 4) * 4;

    float acc[4][4];
    #pragma unroll
    for (int i = 0; i < 4; i++)
        #pragma unroll
        for (int j = 0; j < 4; j++) acc[i][j] = 0.f;

    int ldnode = tid >> 3;
    int kq = tid & 7;

    for (int kk = 0; kk < IN_CH; kk += KT) {
        {
            const float4* wg = (const float4*)(W1 + (size_t)kk * 64);
            float4* wsv = (float4*)Ws;
            wsv[tid] = wg[tid];
            wsv[tid + 256] = wg[tid + 256];
        }
        #pragma unroll
        for (int half = 0; half < 2; half++) {
            int n = ldnode + half * 32;
            int gnode = node0 + n;
            float4 v = (gnode < N)
                ? *(const float4*)(x + (size_t)gnode * IN_CH + kk + kq * 4)
                : make_float4(0.f, 0.f, 0.f, 0.f);
            Xs[kq * 4 + 0][n] = v.x;
            Xs[kq * 4 + 1][n] = v.y;
            Xs[kq * 4 + 2][n] = v.z;
            Xs[kq * 4 + 3][n] = v.w;
        }
        __syncthreads();
        #pragma unroll
        for (int k = 0; k < KT; k++) {
            float4 a = *(const float4*)&Xs[k][na];
            float4 b = *(const float4*)&Ws[k][fb];
            acc[0][0] += a.x * b.x; acc[0][1] += a.x * b.y;
            acc[0][2] += a.x * b.z; acc[0][3] += a.x * b.w;
            acc[1][0] += a.y * b.x; acc[1][1] += a.y * b.y;
            acc[1][2] += a.y * b.z; acc[1][3] += a.y * b.w;
            acc[2][0] += a.z * b.x; acc[2][1] += a.z * b.y;
            acc[2][2] += a.z * b.z; acc[2][3] += a.z * b.w;
            acc[3][0] += a.w * b.x; acc[3][1] += a.w * b.y;
            acc[3][2] += a.w * b.z; acc[3][3] += a.w * b.w;
        }
        __syncthreads();
    }
    #pragma unroll
    for (int i = 0; i < 4; i++) {
        int node = node0 + na + i;
        if (node < N)
            *(float4*)(g_h1 + (size_t)node * HID + fb) =
                make_float4(acc[i][0], acc[i][1], acc[i][2], acc[i][3]);
    }
}

// ---- gather layer 1: out1 = relu(dinv^2*h1 + sum norm*h1[src] + b1) -------
// 16 threads per node, each owns one float4 chunk of the 64-feat row.
__global__ __launch_bounds__(256) void k_gather1(const float* __restrict__ b1, int N) {
    int tid = threadIdx.x;
    int li = tid >> 4, c = tid & 15;
    int node = blockIdx.x * 16 + li;
    if (node >= N) return;
    float di = g_dinv[node];
    float s = di * di;
    float4 acc = ((const float4*)(g_h1 + (size_t)node * HID))[c];
    acc.x *= s; acc.y *= s; acc.z *= s; acc.w *= s;
    int e = g_rowstart[node];
    int end = e + g_incnt[node];
    for (; e + 1 < end; e += 2) {
        int2 c0 = g_csr[e], c1 = g_csr[e + 1];
        float n0 = __int_as_float(c0.y), n1 = __int_as_float(c1.y);
        float4 v0 = ((const float4*)(g_h1 + (size_t)c0.x * HID))[c];
        float4 v1 = ((const float4*)(g_h1 + (size_t)c1.x * HID))[c];
        acc.x += v0.x * n0; acc.y += v0.y * n0;
        acc.z += v0.z * n0; acc.w += v0.w * n0;
        acc.x += v1.x * n1; acc.y += v1.y * n1;
        acc.z += v1.z * n1; acc.w += v1.w * n1;
    }
    if (e < end) {
        int2 c0 = g_csr[e];
        float n0 = __int_as_float(c0.y);
        float4 v0 = ((const float4*)(g_h1 + (size_t)c0.x * HID))[c];
        acc.x += v0.x * n0; acc.y += v0.y * n0;
        acc.z += v0.z * n0; acc.w += v0.w * n0;
    }
    float4 b = ((const float4*)b1)[c];
    acc.x = fmaxf(acc.x + b.x, 0.f);
    acc.y = fmaxf(acc.y + b.y, 0.f);
    acc.z = fmaxf(acc.z + b.z, 0.f);
    acc.w = fmaxf(acc.w + b.w, 0.f);
    ((float4*)(g_out1 + (size_t)node * HID))[c] = acc;
}

// ---- GEMM2: h2[N,16] = out1[N,64] @ W2[64,16] -----------------------------
__global__ __launch_bounds__(256) void k_gemm2(const float* __restrict__ W2, int N) {
    __shared__ float Ws[64 * 16];
    __shared__ float ts[16][68];
    int tid = threadIdx.x;
    for (int i = tid; i < 64 * 16; i += 256) Ws[i] = W2[i];
    int node0 = blockIdx.x * 16;
    for (int i = tid; i < 16 * 64; i += 256) {
        int n = i >> 6, k = i & 63;
        int node = node0 + n;
        ts[n][k] = (node < N) ? g_out1[(size_t)node * HID + k] : 0.f;
    }
    __syncthreads();
    int f = tid & 15, n = tid >> 4;
    float accv = 0.f;
    #pragma unroll 16
    for (int k = 0; k < 64; k++) accv += ts[n][k] * Ws[k * 16 + f];
    int node = node0 + n;
    if (node < N) g_h2[(size_t)node * OUT_CH + f] = accv;
}

// ---- gather layer 2: out = dinv^2*h2 + sum norm*h2[src] -------------------
// 4 threads per node, each owns one float4 chunk of the 16-feat row.
__global__ __launch_bounds__(256) void k_gather2(float* __restrict__ out, int N) {
    int tid = threadIdx.x;
    int li = tid >> 2, c = tid & 3;
    int node = blockIdx.x * 64 + li;
    if (node >= N) return;
    float di = g_dinv[node];
    float s = di * di;
    float4 acc = ((const float4*)(g_h2 + (size_t)node * OUT_CH))[c];
    acc.x *= s; acc.y *= s; acc.z *= s; acc.w *= s;
    int e = g_rowstart[node];
    int end = e + g_incnt[node];
    for (; e + 1 < end; e += 2) {
        int2 c0 = g_csr[e], c1 = g_csr[e + 1];
        float n0 = __int_as_float(c0.y), n1 = __int_as_float(c1.y);
        float4 v0 = ((const float4*)(g_h2 + (size_t)c0.x * OUT_CH))[c];
        float4 v1 = ((const float4*)(g_h2 + (size_t)c1.x * OUT_CH))[c];
        acc.x += v0.x * n0; acc.y += v0.y * n0;
        acc.z += v0.z * n0; acc.w += v0.w * n0;
        acc.x += v1.x * n1; acc.y += v1.y * n1;
        acc.z += v1.z * n1; acc.w += v1.w * n1;
    }
    if (e < end) {
        int2 c0 = g_csr[e];
        float n0 = __int_as_float(c0.y);
        float4 v0 = ((const float4*)(g_h2 + (size_t)c0.x * OUT_CH))[c];
        acc.x += v0.x * n0; acc.y += v0.y * n0;
        acc.z += v0.z * n0; acc.w += v0.w * n0;
    }
    ((float4*)(out + (size_t)node * OUT_CH))[c] = acc;
}

// ---- bias + log_softmax (in place on d_out) -------------------------------
__global__ void k_final(float* __restrict__ out, const float* __restrict__ b2, int N) {
    int node = blockIdx.x * blockDim.x + threadIdx.x;
    if (node >= N) return;
    float4* p = (float4*)(out + (size_t)node * OUT_CH);
    const float4* bb = (const float4*)b2;
    float v[16];
    #pragma unroll
    for (int i = 0; i < 4; i++) {
        float4 a = p[i], b = bb[i];
        v[4 * i + 0] = a.x + b.x;
        v[4 * i + 1] = a.y + b.y;
        v[4 * i + 2] = a.z + b.z;
        v[4 * i + 3] = a.w + b.w;
    }
    float m = v[0];
    #pragma unroll
    for (int i = 1; i < 16; i++) m = fmaxf(m, v[i]);
    float s = 0.f;
    #pragma unroll
    for (int i = 0; i < 16; i++) s += expf(v[i] - m);
    float l = m + logf(s);
    #pragma unroll
    for (int i = 0; i < 4; i++) {
        float4 a;
        a.x = v[4 * i + 0] - l;
        a.y = v[4 * i + 1] - l;
        a.z = v[4 * i + 2] - l;
        a.w = v[4 * i + 3] - l;
        p[i] = a;
    }
}

// ---------------------------------------------------------------------------
extern "C" void kernel_launch(void* const* d_in, const int* in_sizes, int n_in,
                              void* d_out, int out_size) {
    const float* x  = (const float*)d_in[0];
    const void*  ei = d_in[1];
    const float* W1 = (const float*)d_in[2];
    const float* b1 = (const float*)d_in[3];
    const float* W2 = (const float*)d_in[4];
    const float* b2 = (const float*)d_in[5];
    float* out = (float*)d_out;

    int N = in_sizes[0] / IN_CH;
    long long E = in_sizes[1] / 2;

    int ncheck = (int)((E < 2048) ? E : 2048);
    int nbN = (N + 255) / 256;
    int nbE = (int)((E + 255) / 256);

    k_detect<<<1, 32>>>(ei, ncheck, N);
    k_zero<<<nbN, 256>>>(N);
    k_prep<<<nbE, 256>>>(ei, E);
    k_dinv<<<nbN, 256>>>(N);
    k_scan_block<<<nbN, 256>>>(N);
    k_scan_sums<<<1, 512>>>(nbN);
    k_scan_add<<<nbN, 256>>>(N);
    k_fill<<<nbE, 256>>>(E);
    k_gemm1<<<(N + 63) / 64, 256>>>(x, W1, N);
    k_gather1<<<(N + 15) / 16, 256>>>(b1, N);
    k_gemm2<<<(N + 15) / 16, 256>>>(W2, N);
    k_gather2<<<(N + 63) / 64, 256>>>(out, N);
    k_final<<<nbN, 256>>>(out, b2, N);
}

// round 4
// speedup vs baseline: 1.6533x; 1.0518x over previous
#include <cuda_runtime.h>

// ---------------------------------------------------------------------------
// GCN 2-layer, round 4: parallel dtype-detect, CSR gather, fused softmax,
// 128x64 register-tiled GEMM1.
// ---------------------------------------------------------------------------

#define MAXN 131072
#define MAXE 4194304
#define IN_CH 256
#define HID 64
#define OUT_CH 16

__device__ float g_h1[(size_t)MAXN * HID];
__device__ float g_out1[(size_t)MAXN * HID];
__device__ float g_h2[(size_t)MAXN * OUT_CH];
__device__ float g_dinv[MAXN];
__device__ int   g_incnt[MAXN];
__device__ int   g_rowstart[MAXN];
__device__ int   g_fill[MAXN];
__device__ int   g_blocksum[1024];
__device__ int2  g_edge[MAXE];   // decoded (src, dst)
__device__ int2  g_csr[MAXE];    // (src, norm-as-bits) grouped by dst
__device__ int   g_is64;

// ---- edge index load, dtype decided at runtime ----------------------------
__device__ __forceinline__ int ldidx(const void* ei, long long i, int is64) {
    if (is64) return (int)__ldg(((const long long*)ei) + i);
    return __ldg(((const int*)ei) + i);
}

// Parallel probe: 256 threads x 8 int64 words. If data is really int32 the
// packed (lo,hi) pairs are out of [0,N) with prob ~1 per word.
__global__ void k_detect(const void* ei, int nwords, int N) {
    const long long* p = (const long long*)ei;
    int tid = threadIdx.x;
    int ok = 1;
    #pragma unroll
    for (int j = 0; j < 8; j++) {
        int i = tid * 8 + j;
        if (i < nwords) {
            long long v = __ldg(p + i);
            if (v < 0 || v >= (long long)N) ok = 0;
        }
    }
    int all = __syncthreads_and(ok);
    if (tid == 0) g_is64 = all;
}

__global__ void k_zero(int N) {
    int i = blockIdx.x * blockDim.x + threadIdx.x;
    if (i < N) g_incnt[i] = 0;
}

// decode edge index once -> packed int2, accumulate in-degree (int atomics)
__global__ void k_prep(const void* ei, long long E) {
    long long e = (long long)blockIdx.x * blockDim.x + threadIdx.x;
    if (e >= E) return;
    int is64 = g_is64;
    int s = ldidx(ei, e, is64);
    int d = ldidx(ei, E + e, is64);
    g_edge[e] = make_int2(s, d);
    atomicAdd(&g_incnt[d], 1);
}

// ---- block scan of g_incnt (also computes dinv) ---------------------------
__global__ void k_scan_block(int N) {
    __shared__ int wsum[8];
    int tid = threadIdx.x;
    int i = blockIdx.x * 256 + tid;
    int v = (i < N) ? g_incnt[i] : 0;
    if (i < N) g_dinv[i] = rsqrtf((float)(v + 1));  // +1 self-loop
    int lane = tid & 31, wid = tid >> 5;
    int x = v;
    #pragma unroll
    for (int o = 1; o < 32; o <<= 1) {
        int y = __shfl_up_sync(0xffffffffu, x, o);
        if (lane >= o) x += y;
    }
    if (lane == 31) wsum[wid] = x;
    __syncthreads();
    if (wid == 0) {
        int s = (lane < 8) ? wsum[lane] : 0;
        #pragma unroll
        for (int o = 1; o < 8; o <<= 1) {
            int y = __shfl_up_sync(0xffffffffu, s, o);
            if (lane >= o) s += y;
        }
        if (lane < 8) wsum[lane] = s;
    }
    __syncthreads();
    int excl = x - v + (wid > 0 ? wsum[wid - 1] : 0);
    if (i < N) g_rowstart[i] = excl;
    if (tid == 255) g_blocksum[blockIdx.x] = excl + v;
}

__global__ void k_scan_sums(int nb) {
    __shared__ int sh[512];
    int tid = threadIdx.x;
    int v = (tid < nb) ? g_blocksum[tid] : 0;
    sh[tid] = v;
    __syncthreads();
    for (int o = 1; o < 512; o <<= 1) {
        int y = (tid >= o) ? sh[tid - o] : 0;
        __syncthreads();
        sh[tid] += y;
        __syncthreads();
    }
    if (tid < nb) g_blocksum[tid] = sh[tid] - v;  // exclusive
}

__global__ void k_scan_add(int N) {
    int i = blockIdx.x * 256 + threadIdx.x;
    if (i < N) {
        int r = g_rowstart[i] + g_blocksum[blockIdx.x];
        g_rowstart[i] = r;
        g_fill[i] = r;
    }
}

// ---- fill CSR: (src, norm) grouped by dst ---------------------------------
__global__ void k_fill(long long E) {
    long long e = (long long)blockIdx.x * blockDim.x + threadIdx.x;
    if (e >= E) return;
    int2 ed = g_edge[e];
    float nrm = g_dinv[ed.x] * g_dinv[ed.y];
    int pos = atomicAdd(&g_fill[ed.y], 1);
    g_csr[pos] = make_int2(ed.x, __float_as_int(nrm));
}

// ---- GEMM1: h1[N,64] = x[N,256] @ W1[256,64] ------------------------------
// Block tile 128 nodes x 64 feats, 256 threads, thread tile 4x8, K tile 16.
#define KT 16
__global__ __launch_bounds__(256) void k_gemm1(const float* __restrict__ x,
                                               const float* __restrict__ W1, int N) {
    __shared__ float Xs[KT][132];  // [k][node], pad keeps float4 align + no conflicts
    __shared__ float Ws[KT][64];   // [k][feat]
    int tid = threadIdx.x;
    int node0 = blockIdx.x * 128;
    int na = (tid & 31) * 4;       // 4-node group
    int fb = (tid >> 5) * 8;       // 8-feat group

    float acc[4][8];
    #pragma unroll
    for (int i = 0; i < 4; i++)
        #pragma unroll
        for (int j = 0; j < 8; j++) acc[i][j] = 0.f;

    for (int kk = 0; kk < IN_CH; kk += KT) {
        // W tile: 16x64 floats = 256 float4
        {
            const float4* wg = (const float4*)(W1 + (size_t)kk * 64);
            ((float4*)Ws)[tid] = wg[tid];
        }
        // X tile: 128 nodes x 16 k = 512 float4, transposed into Xs[k][node]
        #pragma unroll
        for (int half = 0; half < 2; half++) {
            int i = tid + half * 256;
            int n = i >> 2;            // 0..127
            int kq = i & 3;            // float4 index along k
            int gnode = node0 + n;
            float4 v = (gnode < N)
                ? *(const float4*)(x + (size_t)gnode * IN_CH + kk + kq * 4)
                : make_float4(0.f, 0.f, 0.f, 0.f);
            Xs[kq * 4 + 0][n] = v.x;
            Xs[kq * 4 + 1][n] = v.y;
            Xs[kq * 4 + 2][n] = v.z;
            Xs[kq * 4 + 3][n] = v.w;
        }
        __syncthreads();
        #pragma unroll
        for (int k = 0; k < KT; k++) {
            float4 a  = *(const float4*)&Xs[k][na];
            float4 b0 = *(const float4*)&Ws[k][fb];
            float4 b1 = *(const float4*)&Ws[k][fb + 4];
            float av[4] = {a.x, a.y, a.z, a.w};
            float bv[8] = {b0.x, b0.y, b0.z, b0.w, b1.x, b1.y, b1.z, b1.w};
            #pragma unroll
            for (int i = 0; i < 4; i++)
                #pragma unroll
                for (int j = 0; j < 8; j++)
                    acc[i][j] += av[i] * bv[j];
        }
        __syncthreads();
    }
    #pragma unroll
    for (int i = 0; i < 4; i++) {
        int node = node0 + na + i;
        if (node < N) {
            *(float4*)(g_h1 + (size_t)node * HID + fb) =
                make_float4(acc[i][0], acc[i][1], acc[i][2], acc[i][3]);
            *(float4*)(g_h1 + (size_t)node * HID + fb + 4) =
                make_float4(acc[i][4], acc[i][5], acc[i][6], acc[i][7]);
        }
    }
}

// ---- gather layer 1: out1 = relu(dinv^2*h1 + sum norm*h1[src] + b1) -------
// 16 threads per node, each owns one float4 chunk of the 64-feat row.
__global__ __launch_bounds__(256) void k_gather1(const float* __restrict__ b1, int N) {
    int tid = threadIdx.x;
    int li = tid >> 4, c = tid & 15;
    int node = blockIdx.x * 16 + li;
    if (node >= N) return;
    float di = g_dinv[node];
    float s = di * di;
    float4 acc = ((const float4*)(g_h1 + (size_t)node * HID))[c];
    acc.x *= s; acc.y *= s; acc.z *= s; acc.w *= s;
    int e = g_rowstart[node];
    int end = e + g_incnt[node];
    for (; e + 1 < end; e += 2) {
        int2 c0 = g_csr[e], c1 = g_csr[e + 1];
        float n0 = __int_as_float(c0.y), n1 = __int_as_float(c1.y);
        float4 v0 = ((const float4*)(g_h1 + (size_t)c0.x * HID))[c];
        float4 v1 = ((const float4*)(g_h1 + (size_t)c1.x * HID))[c];
        acc.x += v0.x * n0; acc.y += v0.y * n0;
        acc.z += v0.z * n0; acc.w += v0.w * n0;
        acc.x += v1.x * n1; acc.y += v1.y * n1;
        acc.z += v1.z * n1; acc.w += v1.w * n1;
    }
    if (e < end) {
        int2 c0 = g_csr[e];
        float n0 = __int_as_float(c0.y);
        float4 v0 = ((const float4*)(g_h1 + (size_t)c0.x * HID))[c];
        acc.x += v0.x * n0; acc.y += v0.y * n0;
        acc.z += v0.z * n0; acc.w += v0.w * n0;
    }
    float4 b = ((const float4*)b1)[c];
    acc.x = fmaxf(acc.x + b.x, 0.f);
    acc.y = fmaxf(acc.y + b.y, 0.f);
    acc.z = fmaxf(acc.z + b.z, 0.f);
    acc.w = fmaxf(acc.w + b.w, 0.f);
    ((float4*)(g_out1 + (size_t)node * HID))[c] = acc;
}

// ---- GEMM2: h2[N,16] = out1[N,64] @ W2[64,16] -----------------------------
__global__ __launch_bounds__(256) void k_gemm2(const float* __restrict__ W2, int N) {
    __shared__ float Ws[64 * 16];
    __shared__ float ts[16][68];
    int tid = threadIdx.x;
    for (int i = tid; i < 64 * 16; i += 256) Ws[i] = W2[i];
    int node0 = blockIdx.x * 16;
    for (int i = tid; i < 16 * 64; i += 256) {
        int n = i >> 6, k = i & 63;
        int node = node0 + n;
        ts[n][k] = (node < N) ? g_out1[(size_t)node * HID + k] : 0.f;
    }
    __syncthreads();
    int f = tid & 15, n = tid >> 4;
    float accv = 0.f;
    #pragma unroll 16
    for (int k = 0; k < 64; k++) accv += ts[n][k] * Ws[k * 16 + f];
    int node = node0 + n;
    if (node < N) g_h2[(size_t)node * OUT_CH + f] = accv;
}

// ---- gather layer 2 + bias + log_softmax, fused ---------------------------
// 4 threads per node, each owns one float4 chunk of the 16-feat row.
// Softmax reduction via butterfly shuffles within the 4-lane group.
__global__ __launch_bounds__(256) void k_gather2(float* __restrict__ out,
                                                 const float* __restrict__ b2, int N) {
    int tid = threadIdx.x;
    int li = tid >> 2, c = tid & 3;
    int node = blockIdx.x * 64 + li;
    if (node >= N) return;
    float di = g_dinv[node];
    float s = di * di;
    float4 acc = ((const float4*)(g_h2 + (size_t)node * OUT_CH))[c];
    acc.x *= s; acc.y *= s; acc.z *= s; acc.w *= s;
    int e = g_rowstart[node];
    int end = e + g_incnt[node];
    for (; e + 1 < end; e += 2) {
        int2 c0 = g_csr[e], c1 = g_csr[e + 1];
        float n0 = __int_as_float(c0.y), n1 = __int_as_float(c1.y);
        float4 v0 = ((const float4*)(g_h2 + (size_t)c0.x * OUT_CH))[c];
        float4 v1 = ((const float4*)(g_h2 + (size_t)c1.x * OUT_CH))[c];
        acc.x += v0.x * n0; acc.y += v0.y * n0;
        acc.z += v0.z * n0; acc.w += v0.w * n0;
        acc.x += v1.x * n1; acc.y += v1.y * n1;
        acc.z += v1.z * n1; acc.w += v1.w * n1;
    }
    if (e < end) {
        int2 c0 = g_csr[e];
        float n0 = __int_as_float(c0.y);
        float4 v0 = ((const float4*)(g_h2 + (size_t)c0.x * OUT_CH))[c];
        acc.x += v0.x * n0; acc.y += v0.y * n0;
        acc.z += v0.z * n0; acc.w += v0.w * n0;
    }
    float4 b = ((const float4*)b2)[c];
    acc.x += b.x; acc.y += b.y; acc.z += b.z; acc.w += b.w;
    // max over 16 values (4 local + 4-lane butterfly)
    float m = fmaxf(fmaxf(acc.x, acc.y), fmaxf(acc.z, acc.w));
    m = fmaxf(m, __shfl_xor_sync(0xffffffffu, m, 1));
    m = fmaxf(m, __shfl_xor_sync(0xffffffffu, m, 2));
    float se = expf(acc.x - m) + expf(acc.y - m) + expf(acc.z - m) + expf(acc.w - m);
    se += __shfl_xor_sync(0xffffffffu, se, 1);
    se += __shfl_xor_sync(0xffffffffu, se, 2);
    float l = m + logf(se);
    acc.x -= l; acc.y -= l; acc.z -= l; acc.w -= l;
    ((float4*)(out + (size_t)node * OUT_CH))[c] = acc;
}

// ---------------------------------------------------------------------------
extern "C" void kernel_launch(void* const* d_in, const int* in_sizes, int n_in,
                              void* d_out, int out_size) {
    const float* x  = (const float*)d_in[0];
    const void*  ei = d_in[1];
    const float* W1 = (const float*)d_in[2];
    const float* b1 = (const float*)d_in[3];
    const float* W2 = (const float*)d_in[4];
    const float* b2 = (const float*)d_in[5];
    float* out = (float*)d_out;

    int N = in_sizes[0] / IN_CH;
    long long E = in_sizes[1] / 2;

    int nwords = (int)((E < 2048) ? E : 2048);
    int nbN = (N + 255) / 256;
    int nbE = (int)((E + 255) / 256);

    k_detect<<<1, 256>>>(ei, nwords, N);
    k_zero<<<nbN, 256>>>(N);
    k_prep<<<nbE, 256>>>(ei, E);
    k_scan_block<<<nbN, 256>>>(N);
    k_scan_sums<<<1, 512>>>(nbN);
    k_scan_add<<<nbN, 256>>>(N);
    k_fill<<<nbE, 256>>>(E);
    k_gemm1<<<(N + 127) / 128, 256>>>(x, W1, N);
    k_gather1<<<(N + 15) / 16, 256>>>(b1, N);
    k_gemm2<<<(N + 15) / 16, 256>>>(W2, N);
    k_gather2<<<(N + 63) / 64, 256>>>(out, b2, N);
}

// round 5
// speedup vs baseline: 1.8581x; 1.1239x over previous
#include <cuda_runtime.h>

// ---------------------------------------------------------------------------
// GCN 2-layer, round 5: 7 launches. gemm1 overlapped with CSR fill in one
// kernel; gemm2 fused into gather1; scan_add inlined into consumers.
// ---------------------------------------------------------------------------

#define MAXN 131072
#define MAXE 4194304
#define IN_CH 256
#define HID 64
#define OUT_CH 16

__device__ float g_h1[(size_t)MAXN * HID];
__device__ float g_h2[(size_t)MAXN * OUT_CH];
__device__ float g_dinv[MAXN];
__device__ int   g_incnt[MAXN];
__device__ int   g_rowstart[MAXN];   // block-local exclusive prefix
__device__ int   g_fill[MAXN];       // slot counters (zeroed)
__device__ int   g_blocksum[1024];   // exclusive block prefix after k_scan_sums
__device__ int2  g_edge[MAXE];       // decoded (src, dst)
__device__ int2  g_csr[MAXE];        // (src, norm-as-bits) grouped by dst
__device__ int   g_is64;

__device__ __forceinline__ int ldidx(const void* ei, long long i, int is64) {
    if (is64) return (int)__ldg(((const long long*)ei) + i);
    return __ldg(((const int*)ei) + i);
}

// full rowstart for node i (after k_scan_sums)
__device__ __forceinline__ int rowstart(int i) {
    return g_rowstart[i] + g_blocksum[i >> 8];
}

// ---- init: zero counters; block 0 also probes edge dtype ------------------
__global__ void k_init(const void* ei, int nwords, int N) {
    int i = blockIdx.x * blockDim.x + threadIdx.x;
    if (i < N) { g_incnt[i] = 0; g_fill[i] = 0; }
    if (blockIdx.x == 0) {
        const long long* p = (const long long*)ei;
        int tid = threadIdx.x;
        int ok = 1;
        #pragma unroll
        for (int j = 0; j < 8; j++) {
            int w = tid * 8 + j;
            if (w < nwords) {
                long long v = __ldg(p + w);
                if (v < 0 || v >= (long long)N) ok = 0;
            }
        }
        int all = __syncthreads_and(ok);
        if (tid == 0) g_is64 = all;
    }
}

// ---- decode edges once, accumulate in-degree ------------------------------
__global__ void k_prep(const void* ei, long long E) {
    long long e = (long long)blockIdx.x * blockDim.x + threadIdx.x;
    if (e >= E) return;
    int is64 = g_is64;
    int s = ldidx(ei, e, is64);
    int d = ldidx(ei, E + e, is64);
    g_edge[e] = make_int2(s, d);
    atomicAdd(&g_incnt[d], 1);
}

// ---- block-local scan of g_incnt; also computes dinv ----------------------
__global__ void k_scan_block(int N) {
    __shared__ int wsum[8];
    int tid = threadIdx.x;
    int i = blockIdx.x * 256 + tid;
    int v = (i < N) ? g_incnt[i] : 0;
    if (i < N) g_dinv[i] = rsqrtf((float)(v + 1));  // +1 self-loop
    int lane = tid & 31, wid = tid >> 5;
    int x = v;
    #pragma unroll
    for (int o = 1; o < 32; o <<= 1) {
        int y = __shfl_up_sync(0xffffffffu, x, o);
        if (lane >= o) x += y;
    }
    if (lane == 31) wsum[wid] = x;
    __syncthreads();
    if (wid == 0) {
        int s = (lane < 8) ? wsum[lane] : 0;
        #pragma unroll
        for (int o = 1; o < 8; o <<= 1) {
            int y = __shfl_up_sync(0xffffffffu, s, o);
            if (lane >= o) s += y;
        }
        if (lane < 8) wsum[lane] = s;
    }
    __syncthreads();
    int excl = x - v + (wid > 0 ? wsum[wid - 1] : 0);
    if (i < N) g_rowstart[i] = excl;
    if (tid == 255) g_blocksum[blockIdx.x] = excl + v;
}

__global__ void k_scan_sums(int nb) {
    __shared__ int sh[512];
    int tid = threadIdx.x;
    int v = (tid < nb) ? g_blocksum[tid] : 0;
    sh[tid] = v;
    __syncthreads();
    for (int o = 1; o < 512; o <<= 1) {
        int y = (tid >= o) ? sh[tid - o] : 0;
        __syncthreads();
        sh[tid] += y;
        __syncthreads();
    }
    if (tid < nb) g_blocksum[tid] = sh[tid] - v;  // exclusive
}

// ---- mega: gemm1 (blocks [0,nbG)) || CSR fill (blocks [nbG, nbG+nbF)) -----
// gemm1: h1[N,64] = x[N,256] @ W1[256,64]; 128x64 tile, 4x8 micro, KT=16.
#define KT 16
#define FILL_PER_BLK 1024
__global__ __launch_bounds__(256) void k_mega(const float* __restrict__ x,
                                              const float* __restrict__ W1,
                                              int N, int nbG, long long E) {
    __shared__ float Xs[KT][132];
    __shared__ float Ws[KT][64];
    int tid = threadIdx.x;

    if (blockIdx.x >= nbG) {
        // -------- fill path: 4 edges per thread --------
        long long base = (long long)(blockIdx.x - nbG) * FILL_PER_BLK + tid * 4;
        #pragma unroll
        for (int half = 0; half < 2; half++) {
            long long e0 = base + half * 2;
            if (e0 < E) {
                int4 two = *(const int4*)&g_edge[e0];   // 2 edges
                // edge A
                {
                    int s = two.x, d = two.y;
                    float nrm = g_dinv[s] * g_dinv[d];
                    int pos = rowstart(d) + atomicAdd(&g_fill[d], 1);
                    g_csr[pos] = make_int2(s, __float_as_int(nrm));
                }
                // edge B
                if (e0 + 1 < E) {
                    int s = two.z, d = two.w;
                    float nrm = g_dinv[s] * g_dinv[d];
                    int pos = rowstart(d) + atomicAdd(&g_fill[d], 1);
                    g_csr[pos] = make_int2(s, __float_as_int(nrm));
                }
            }
        }
        return;
    }

    // -------- gemm1 path --------
    int node0 = blockIdx.x * 128;
    int na = (tid & 31) * 4;
    int fb = (tid >> 5) * 8;

    float acc[4][8];
    #pragma unroll
    for (int i = 0; i < 4; i++)
        #pragma unroll
        for (int j = 0; j < 8; j++) acc[i][j] = 0.f;

    for (int kk = 0; kk < IN_CH; kk += KT) {
        {
            const float4* wg = (const float4*)(W1 + (size_t)kk * 64);
            ((float4*)Ws)[tid] = wg[tid];
        }
        #pragma unroll
        for (int half = 0; half < 2; half++) {
            int i = tid + half * 256;
            int n = i >> 2;
            int kq = i & 3;
            int gnode = node0 + n;
            float4 v = (gnode < N)
                ? *(const float4*)(x + (size_t)gnode * IN_CH + kk + kq * 4)
                : make_float4(0.f, 0.f, 0.f, 0.f);
            Xs[kq * 4 + 0][n] = v.x;
            Xs[kq * 4 + 1][n] = v.y;
            Xs[kq * 4 + 2][n] = v.z;
            Xs[kq * 4 + 3][n] = v.w;
        }
        __syncthreads();
        #pragma unroll
        for (int k = 0; k < KT; k++) {
            float4 a  = *(const float4*)&Xs[k][na];
            float4 b0 = *(const float4*)&Ws[k][fb];
            float4 b1v = *(const float4*)&Ws[k][fb + 4];
            float av[4] = {a.x, a.y, a.z, a.w};
            float bv[8] = {b0.x, b0.y, b0.z, b0.w, b1v.x, b1v.y, b1v.z, b1v.w};
            #pragma unroll
            for (int i = 0; i < 4; i++)
                #pragma unroll
                for (int j = 0; j < 8; j++)
                    acc[i][j] += av[i] * bv[j];
        }
        __syncthreads();
    }
    #pragma unroll
    for (int i = 0; i < 4; i++) {
        int node = node0 + na + i;
        if (node < N) {
            *(float4*)(g_h1 + (size_t)node * HID + fb) =
                make_float4(acc[i][0], acc[i][1], acc[i][2], acc[i][3]);
            *(float4*)(g_h1 + (size_t)node * HID + fb + 4) =
                make_float4(acc[i][4], acc[i][5], acc[i][6], acc[i][7]);
        }
    }
}

// ---- gather1 + gemm2 fused ------------------------------------------------
// 16 nodes/block, 16 threads/node. Phase 1: t = relu(dinv^2*h1 + sum + b1)
// into smem. Phase 2: h2[node][f] = dot(t, W2[:,f]) per thread.
__global__ __launch_bounds__(256) void k_g1g2(const float* __restrict__ b1,
                                              const float* __restrict__ W2, int N) {
    __shared__ float ts[16][68];
    __shared__ float W2t[16][68];   // transposed W2: [f][k]
    __shared__ float b1s[64];
    int tid = threadIdx.x;
    for (int i = tid; i < 64 * 16; i += 256) W2t[i & 15][i >> 4] = W2[i];
    if (tid < 64) b1s[tid] = b1[tid];

    int li = tid >> 4, c = tid & 15;
    int node = blockIdx.x * 16 + li;
    bool valid = node < N;
    if (!valid) node = N - 1;       // clamp: redundant-but-valid work, no divergence at syncs

    float di = g_dinv[node];
    float s = di * di;
    float4 acc = ((const float4*)(g_h1 + (size_t)node * HID))[c];
    acc.x *= s; acc.y *= s; acc.z *= s; acc.w *= s;
    int e = rowstart(node);
    int end = e + g_incnt[node];
    for (; e + 1 < end; e += 2) {
        int2 c0 = g_csr[e], c1 = g_csr[e + 1];
        float n0 = __int_as_float(c0.y), n1 = __int_as_float(c1.y);
        float4 v0 = ((const float4*)(g_h1 + (size_t)c0.x * HID))[c];
        float4 v1 = ((const float4*)(g_h1 + (size_t)c1.x * HID))[c];
        acc.x += v0.x * n0; acc.y += v0.y * n0;
        acc.z += v0.z * n0; acc.w += v0.w * n0;
        acc.x += v1.x * n1; acc.y += v1.y * n1;
        acc.z += v1.z * n1; acc.w += v1.w * n1;
    }
    if (e < end) {
        int2 c0 = g_csr[e];
        float n0 = __int_as_float(c0.y);
        float4 v0 = ((const float4*)(g_h1 + (size_t)c0.x * HID))[c];
        acc.x += v0.x * n0; acc.y += v0.y * n0;
        acc.z += v0.z * n0; acc.w += v0.w * n0;
    }
    float4 b = *(const float4*)&b1s[c * 4];
    acc.x = fmaxf(acc.x + b.x, 0.f);
    acc.y = fmaxf(acc.y + b.y, 0.f);
    acc.z = fmaxf(acc.z + b.z, 0.f);
    acc.w = fmaxf(acc.w + b.w, 0.f);
    *(float4*)&ts[li][c * 4] = acc;
    __syncthreads();

    // phase 2: thread computes h2[node][c] = sum_k ts[li][k] * W2t[c][k]
    float h2 = 0.f;
    #pragma unroll
    for (int k = 0; k < 64; k += 4) {
        float4 t = *(const float4*)&ts[li][k];
        float4 w = *(const float4*)&W2t[c][k];
        h2 += t.x * w.x + t.y * w.y + t.z * w.z + t.w * w.w;
    }
    if (valid) g_h2[(size_t)node * OUT_CH + c] = h2;
}

// ---- gather2 + bias + log_softmax fused -----------------------------------
// 4 threads/node; softmax via 4-lane butterfly shuffles (N % 8 == 0 assumed
// for full-warp exit granularity; holds for this problem).
__global__ __launch_bounds__(256) void k_gather2(float* __restrict__ out,
                                                 const float* __restrict__ b2, int N) {
    int tid = threadIdx.x;
    int li = tid >> 2, c = tid & 3;
    int node = blockIdx.x * 64 + li;
    if (node >= N) return;
    float di = g_dinv[node];
    float s = di * di;
    float4 acc = ((const float4*)(g_h2 + (size_t)node * OUT_CH))[c];
    acc.x *= s; acc.y *= s; acc.z *= s; acc.w *= s;
    int e = rowstart(node);
    int end = e + g_incnt[node];
    for (; e + 1 < end; e += 2) {
        int2 c0 = g_csr[e], c1 = g_csr[e + 1];
        float n0 = __int_as_float(c0.y), n1 = __int_as_float(c1.y);
        float4 v0 = ((const float4*)(g_h2 + (size_t)c0.x * OUT_CH))[c];
        float4 v1 = ((const float4*)(g_h2 + (size_t)c1.x * OUT_CH))[c];
        acc.x += v0.x * n0; acc.y += v0.y * n0;
        acc.z += v0.z * n0; acc.w += v0.w * n0;
        acc.x += v1.x * n1; acc.y += v1.y * n1;
        acc.z += v1.z * n1; acc.w += v1.w * n1;
    }
    if (e < end) {
        int2 c0 = g_csr[e];
        float n0 = __int_as_float(c0.y);
        float4 v0 = ((const float4*)(g_h2 + (size_t)c0.x * OUT_CH))[c];
        acc.x += v0.x * n0; acc.y += v0.y * n0;
        acc.z += v0.z * n0; acc.w += v0.w * n0;
    }
    float4 b = ((const float4*)b2)[c];
    acc.x += b.x; acc.y += b.y; acc.z += b.z; acc.w += b.w;
    float m = fmaxf(fmaxf(acc.x, acc.y), fmaxf(acc.z, acc.w));
    m = fmaxf(m, __shfl_xor_sync(0xffffffffu, m, 1));
    m = fmaxf(m, __shfl_xor_sync(0xffffffffu, m, 2));
    float se = expf(acc.x - m) + expf(acc.y - m) + expf(acc.z - m) + expf(acc.w - m);
    se += __shfl_xor_sync(0xffffffffu, se, 1);
    se += __shfl_xor_sync(0xffffffffu, se, 2);
    float l = m + logf(se);
    acc.x -= l; acc.y -= l; acc.z -= l; acc.w -= l;
    ((float4*)(out + (size_t)node * OUT_CH))[c] = acc;
}

// ---------------------------------------------------------------------------
extern "C" void kernel_launch(void* const* d_in, const int* in_sizes, int n_in,
                              void* d_out, int out_size) {
    const float* x  = (const float*)d_in[0];
    const void*  ei = d_in[1];
    const float* W1 = (const float*)d_in[2];
    const float* b1 = (const float*)d_in[3];
    const float* W2 = (const float*)d_in[4];
    const float* b2 = (const float*)d_in[5];
    float* out = (float*)d_out;

    int N = in_sizes[0] / IN_CH;
    long long E = in_sizes[1] / 2;

    int nwords = (int)((E < 2048) ? E : 2048);
    int nbN = (N + 255) / 256;
    int nbE = (int)((E + 255) / 256);
    int nbG = (N + 127) / 128;
    int nbF = (int)((E + FILL_PER_BLK - 1) / FILL_PER_BLK);

    k_init<<<nbN, 256>>>(ei, nwords, N);
    k_prep<<<nbE, 256>>>(ei, E);
    k_scan_block<<<nbN, 256>>>(N);
    k_scan_sums<<<1, 512>>>(nbN);
    k_mega<<<nbG + nbF, 256>>>(x, W1, N, nbG, E);
    k_g1g2<<<(N + 15) / 16, 256>>>(b1, W2, N);
    k_gather2<<<(N + 63) / 64, 256>>>(out, b2, N);
}